// round 11
// baseline (speedup 1.0000x reference)
#include <cuda_runtime.h>
#include <cuda_bf16.h>
#include <cstdint>

#define N_NODES 50000
#define N_EDGES 800000
#define N_PAIRS 100000
#define IN_CH 128
#define HID 256
#define EMB 32
#define CAT_EMB 8
#define MAX_TOK 20

// bf16 rows. hcat0: [agg(160) | x(128) gwas(32)] = 320 bf16 (640 B)
//            hcat1: [agg(256) | h1(256)] = 512 bf16 (1 KB)
__device__ __align__(16) __nv_bfloat16 g_hcat0[(size_t)N_NODES * 320];
__device__ __align__(16) __nv_bfloat16 g_hcat1[(size_t)N_NODES * 512];
__device__ __align__(16) __nv_bfloat16 g_z[(size_t)N_NODES * HID];
// CSR for in-edges (dst -> list of src)
__device__ __align__(16) int g_deg[N_NODES];
__device__ int g_off[N_NODES + 1];
__device__ int g_cur[N_NODES];
__device__ int g_nbr[N_EDGES];
#define SCAN_BLOCKS 49
__device__ int g_bsum[SCAN_BLOCKS];
__device__ int g_bpre[SCAN_BLOCKS];
// stacked transposed weights, K-major bf16
__device__ __align__(16) __nv_bfloat16 g_Wt0[(size_t)HID * 320];
__device__ __align__(16) __nv_bfloat16 g_Wt1[(size_t)HID * 512];

// ---------------------------------------------------------------------------
// Streams/events for the forked launch DAG (created at program load).
// ---------------------------------------------------------------------------
static cudaStream_t g_s1, g_s2;
static cudaEvent_t g_eFork, g_eCSR, g_eW0, g_eW1;
namespace {
struct StreamInit {
    StreamInit() {
        cudaStreamCreateWithFlags(&g_s1, cudaStreamNonBlocking);
        cudaStreamCreateWithFlags(&g_s2, cudaStreamNonBlocking);
        cudaEventCreateWithFlags(&g_eFork, cudaEventDisableTiming);
        cudaEventCreateWithFlags(&g_eCSR, cudaEventDisableTiming);
        cudaEventCreateWithFlags(&g_eW0, cudaEventDisableTiming);
        cudaEventCreateWithFlags(&g_eW1, cudaEventDisableTiming);
    }
};
StreamInit g_stream_init;
}  // namespace

// ---------------------------------------------------------------------------
// GWAS encoder (one warp/node, linearity-rewritten) + concat(x) -> hcat0.
// ---------------------------------------------------------------------------
#define GWAS_BLOCKS (N_NODES / 8)

__global__ void gwas_kernel(const float* __restrict__ x,
                            const int* __restrict__ tok,
                            const float* __restrict__ sc,
                            const int* __restrict__ cat,
                            const float* __restrict__ tE,
                            const float* __restrict__ cE,
                            const float* __restrict__ pW,
                            const float* __restrict__ pb) {
    int node = (int)(((size_t)blockIdx.x * blockDim.x + threadIdx.x) >> 5);
    int lane = threadIdx.x & 31;
    if (node >= N_NODES) return;

    float4 xv = ((const float4*)(x + (size_t)node * IN_CH))[lane];
    uint2 xp;
    {
        __nv_bfloat162 lo = __floats2bfloat162_rn(xv.x, xv.y);
        __nv_bfloat162 hi = __floats2bfloat162_rn(xv.z, xv.w);
        xp.x = *reinterpret_cast<uint32_t*>(&lo);
        xp.y = *reinterpret_cast<uint32_t*>(&hi);
    }
    *(uint2*)(g_hcat0 + (size_t)node * 320 + 160 + 4 * lane) = xp;

    float ts = 0.f, cs = 0.f, ssum = 0.f, wsum = 0.f;
#pragma unroll 4
    for (int t = 0; t < MAX_TOK; t++) {
        int id  = tok[(size_t)node * MAX_TOK + t];
        float s = sc[(size_t)node * MAX_TOK + t];
        int cid = cat[(size_t)node * MAX_TOK + t];
        float te = tE[(size_t)id * EMB + lane];
        float ce = (lane < CAT_EMB) ? cE[cid * CAT_EMB + lane] : 0.f;
        float wt = (id != 0) ? s : 0.f;
        ts += wt * te;
        cs += wt * ce;
        ssum += wt * s;
        wsum += wt;
    }

    float w[41];
#pragma unroll
    for (int k = 0; k < 41; k++) w[k] = pW[k * EMB + lane];
    float acc = wsum * pb[lane] + ssum * w[40];
#pragma unroll
    for (int k = 0; k < 32; k++)
        acc += __shfl_sync(0xffffffffu, ts, k) * w[k];
#pragma unroll
    for (int k = 0; k < 8; k++)
        acc += __shfl_sync(0xffffffffu, cs, k) * w[32 + k];

    g_hcat0[(size_t)node * 320 + 288 + lane] =
        __float2bfloat16(acc / fmaxf(wsum, 1e-8f));
}

// ---------------------------------------------------------------------------
// CSR build: zero -> count -> two-level scan (A/B/C) -> fill
// ---------------------------------------------------------------------------
__global__ void zero_deg_kernel() {
    int i = blockIdx.x * blockDim.x + threadIdx.x;
    if (i < N_NODES / 4) ((uint4*)g_deg)[i] = make_uint4(0, 0, 0, 0);
}

__global__ void count_kernel(const int* __restrict__ edst) {
    int i = blockIdx.x * blockDim.x + threadIdx.x;
    if (i < N_EDGES) atomicAdd(&g_deg[edst[i]], 1);
}

__global__ void __launch_bounds__(1024, 1) scanA_kernel() {
    __shared__ int wsum[32];
    int tid = threadIdx.x, lane = tid & 31, w = tid >> 5;
    int i = blockIdx.x * 1024 + tid;
    int v = (i < N_NODES) ? g_deg[i] : 0;
    int xx = v;
#pragma unroll
    for (int o = 1; o < 32; o <<= 1) {
        int t = __shfl_up_sync(0xffffffffu, xx, o);
        if (lane >= o) xx += t;
    }
    if (lane == 31) wsum[w] = xx;
    __syncthreads();
    if (w == 0) {
        int s = wsum[lane];
#pragma unroll
        for (int o = 1; o < 32; o <<= 1) {
            int t = __shfl_up_sync(0xffffffffu, s, o);
            if (lane >= o) s += t;
        }
        wsum[lane] = s;
    }
    __syncthreads();
    int incl = xx + ((w > 0) ? wsum[w - 1] : 0);
    if (i < N_NODES) g_cur[i] = incl - v;           // exclusive within block
    if (tid == 1023) g_bsum[blockIdx.x] = incl;     // block total
}

__global__ void scanB_kernel() {
    int lane = threadIdx.x;
    int v0 = (lane < SCAN_BLOCKS) ? g_bsum[lane] : 0;
    int v1 = (32 + lane < SCAN_BLOCKS) ? g_bsum[32 + lane] : 0;
    int x0 = v0;
#pragma unroll
    for (int o = 1; o < 32; o <<= 1) {
        int t = __shfl_up_sync(0xffffffffu, x0, o);
        if (lane >= o) x0 += t;
    }
    int tot0 = __shfl_sync(0xffffffffu, x0, 31);
    int x1 = v1;
#pragma unroll
    for (int o = 1; o < 32; o <<= 1) {
        int t = __shfl_up_sync(0xffffffffu, x1, o);
        if (lane >= o) x1 += t;
    }
    if (lane < SCAN_BLOCKS) g_bpre[lane] = x0 - v0;
    if (32 + lane < SCAN_BLOCKS) g_bpre[32 + lane] = tot0 + x1 - v1;
    if (lane == SCAN_BLOCKS - 32 - 1)
        g_off[N_NODES] = tot0 + x1;
}

__global__ void __launch_bounds__(1024, 1) scanC_kernel() {
    int i = blockIdx.x * 1024 + threadIdx.x;
    if (i < N_NODES) {
        int e = g_cur[i] + g_bpre[blockIdx.x];
        g_off[i] = e;
        g_cur[i] = e;
    }
}

__global__ void fill_kernel(const int* __restrict__ esrc,
                            const int* __restrict__ edst) {
    int i = blockIdx.x * blockDim.x + threadIdx.x;
    if (i < N_EDGES) {
        int p = atomicAdd(&g_cur[edst[i]], 1);
        g_nbr[p] = esrc[i];
    }
}

// ---------------------------------------------------------------------------
// Stack + transpose weights into K-major bf16 [HID, K].
// ---------------------------------------------------------------------------
__global__ void wstack_kernel(const float* __restrict__ Wl,
                              const float* __restrict__ Wr,
                              __nv_bfloat16* __restrict__ out, int K1, int K) {
    __shared__ float t[32][33];
    int kb = blockIdx.x * 32, nb = blockIdx.y * 32;
    for (int dy = threadIdx.y; dy < 32; dy += 8) {
        int k = kb + dy, n = nb + threadIdx.x;
        t[dy][threadIdx.x] = (k < K1) ? Wl[(size_t)k * HID + n]
                                      : Wr[(size_t)(k - K1) * HID + n];
    }
    __syncthreads();
    for (int dy = threadIdx.y; dy < 32; dy += 8) {
        int n = nb + dy, k = kb + threadIdx.x;
        out[(size_t)n * K + k] = __float2bfloat16(t[threadIdx.x][dy]);
    }
}

// ---------------------------------------------------------------------------
// CSR gather-aggregate, 4-way unrolled neighbor loop (MLP=4).
// Flattened named accumulators (no local-array indexing), scalar tail.
// ---------------------------------------------------------------------------
template <int LAYER>
__global__ void gather_kernel() {
    constexpr int CHUNKS = (LAYER == 0) ? 20 : 32;
    constexpr int EPB    = 256 / CHUNKS;
    constexpr int ROWE   = (LAYER == 0) ? 320 : 512;
    constexpr int FOFF   = (LAYER == 0) ? 160 : 256;
    __nv_bfloat16* base = (LAYER == 0) ? g_hcat0 : g_hcat1;

    int tid = threadIdx.x;
    int el = tid / CHUNKS;
    int q  = tid - el * CHUNKS;
    if (el >= EPB) return;
    int n = blockIdx.x * EPB + el;
    if (n >= N_NODES) return;

    int beg = g_off[n], end = g_off[n + 1];
    const __nv_bfloat16* fb = base + FOFF + 8 * q;

    __nv_bfloat162 z2 = __floats2bfloat162_rn(0.f, 0.f);
    __nv_bfloat162 p0 = z2, p1 = z2, p2 = z2, p3 = z2;   // leg 0
    __nv_bfloat162 q0 = z2, q1 = z2, q2 = z2, q3 = z2;   // leg 1
    __nv_bfloat162 r0 = z2, r1 = z2, r2 = z2, r3 = z2;   // leg 2
    __nv_bfloat162 t0 = z2, t1 = z2, t2 = z2, t3 = z2;   // leg 3

    int j = beg;
    for (; j + 4 <= end; j += 4) {
        int s0 = g_nbr[j];
        int s1 = g_nbr[j + 1];
        int s2 = g_nbr[j + 2];
        int s3 = g_nbr[j + 3];
        uint4 v0 = *(const uint4*)(fb + (size_t)s0 * ROWE);
        uint4 v1 = *(const uint4*)(fb + (size_t)s1 * ROWE);
        uint4 v2 = *(const uint4*)(fb + (size_t)s2 * ROWE);
        uint4 v3 = *(const uint4*)(fb + (size_t)s3 * ROWE);
        p0 = __hadd2(p0, *reinterpret_cast<__nv_bfloat162*>(&v0.x));
        p1 = __hadd2(p1, *reinterpret_cast<__nv_bfloat162*>(&v0.y));
        p2 = __hadd2(p2, *reinterpret_cast<__nv_bfloat162*>(&v0.z));
        p3 = __hadd2(p3, *reinterpret_cast<__nv_bfloat162*>(&v0.w));
        q0 = __hadd2(q0, *reinterpret_cast<__nv_bfloat162*>(&v1.x));
        q1 = __hadd2(q1, *reinterpret_cast<__nv_bfloat162*>(&v1.y));
        q2 = __hadd2(q2, *reinterpret_cast<__nv_bfloat162*>(&v1.z));
        q3 = __hadd2(q3, *reinterpret_cast<__nv_bfloat162*>(&v1.w));
        r0 = __hadd2(r0, *reinterpret_cast<__nv_bfloat162*>(&v2.x));
        r1 = __hadd2(r1, *reinterpret_cast<__nv_bfloat162*>(&v2.y));
        r2 = __hadd2(r2, *reinterpret_cast<__nv_bfloat162*>(&v2.z));
        r3 = __hadd2(r3, *reinterpret_cast<__nv_bfloat162*>(&v2.w));
        t0 = __hadd2(t0, *reinterpret_cast<__nv_bfloat162*>(&v3.x));
        t1 = __hadd2(t1, *reinterpret_cast<__nv_bfloat162*>(&v3.y));
        t2 = __hadd2(t2, *reinterpret_cast<__nv_bfloat162*>(&v3.z));
        t3 = __hadd2(t3, *reinterpret_cast<__nv_bfloat162*>(&v3.w));
    }
    for (; j < end; j++) {
        int s = g_nbr[j];
        uint4 v = *(const uint4*)(fb + (size_t)s * ROWE);
        p0 = __hadd2(p0, *reinterpret_cast<__nv_bfloat162*>(&v.x));
        p1 = __hadd2(p1, *reinterpret_cast<__nv_bfloat162*>(&v.y));
        p2 = __hadd2(p2, *reinterpret_cast<__nv_bfloat162*>(&v.z));
        p3 = __hadd2(p3, *reinterpret_cast<__nv_bfloat162*>(&v.w));
    }
    p0 = __hadd2(__hadd2(p0, q0), __hadd2(r0, t0));
    p1 = __hadd2(__hadd2(p1, q1), __hadd2(r1, t1));
    p2 = __hadd2(__hadd2(p2, q2), __hadd2(r2, t2));
    p3 = __hadd2(__hadd2(p3, q3), __hadd2(r3, t3));

    int d = end - beg;
    float rv = 1.f / (float)((d > 1) ? d : 1);
    uint4 o;
    {
        float2 f;
        __nv_bfloat162 r;
        f = __bfloat1622float2(p0); r = __floats2bfloat162_rn(f.x * rv, f.y * rv);
        o.x = *reinterpret_cast<uint32_t*>(&r);
        f = __bfloat1622float2(p1); r = __floats2bfloat162_rn(f.x * rv, f.y * rv);
        o.y = *reinterpret_cast<uint32_t*>(&r);
        f = __bfloat1622float2(p2); r = __floats2bfloat162_rn(f.x * rv, f.y * rv);
        o.z = *reinterpret_cast<uint32_t*>(&r);
        f = __bfloat1622float2(p3); r = __floats2bfloat162_rn(f.x * rv, f.y * rv);
        o.w = *reinterpret_cast<uint32_t*>(&r);
    }
    *(uint4*)(base + (size_t)n * ROWE + 8 * q) = o;
}

// ---------------------------------------------------------------------------
// bf16 mma.sync GEMM, 5-stage cp.async pipeline (dynamic smem, 100 KB).
// BM=128 BN=128 BK=32, 256 threads (8 warps 2x4), warp tile 64x32, m16n8k16.
// ---------------------------------------------------------------------------
#define NSTAGE 5
#define GEMM_SMEM_BYTES (2 * NSTAGE * 2560 * 4)

template <int KTOT, int LDC, int COFF>
__global__ void __launch_bounds__(256, 2)
tc_gemm(const __nv_bfloat16* __restrict__ A, const __nv_bfloat16* __restrict__ Bt,
        const float* __restrict__ bias, __nv_bfloat16* __restrict__ C) {
    extern __shared__ uint32_t sm[];
    const int tid = threadIdx.x;
    const int wid = tid >> 5, lane = tid & 31;
    const int g = lane >> 2, tg = lane & 3;
    const int warp_m = wid >> 2, warp_n = wid & 3;
    const int row0 = blockIdx.x * 128;
    const int col0 = blockIdx.y * 128;

    float acc[4][4][4];
#pragma unroll
    for (int mi = 0; mi < 4; mi++)
#pragma unroll
        for (int ni = 0; ni < 4; ni++)
#pragma unroll
            for (int q = 0; q < 4; q++) acc[mi][ni][q] = 0.f;

    constexpr int NCHUNK = KTOT / 32;

    auto issue_chunk = [&](int c) {
        int st = c % NSTAGE;
        int k0 = c * 32;
#pragma unroll
        for (int i = 0; i < 2; i++) {
            int idx = tid + i * 256;
            int r = idx >> 2, c4 = idx & 3;
            int gr = row0 + r;
            int grc = (gr < N_NODES) ? gr : (N_NODES - 1);
            const __nv_bfloat16* gp = A + (size_t)grc * KTOT + k0 + c4 * 8;
            uint32_t sa = (uint32_t)__cvta_generic_to_shared(
                &sm[st * 2560 + r * 20 + c4 * 4]);
            int sz = (gr < N_NODES) ? 16 : 0;
            asm volatile("cp.async.cg.shared.global [%0], [%1], 16, %2;"
                         :: "r"(sa), "l"(gp), "r"(sz));
        }
#pragma unroll
        for (int i = 0; i < 2; i++) {
            int idx = tid + i * 256;
            int n = idx >> 2, c4 = idx & 3;
            const __nv_bfloat16* gp = Bt + (size_t)(col0 + n) * KTOT + k0 + c4 * 8;
            uint32_t sa = (uint32_t)__cvta_generic_to_shared(
                &sm[(NSTAGE + st) * 2560 + n * 20 + c4 * 4]);
            asm volatile("cp.async.cg.shared.global [%0], [%1], 16;"
                         :: "r"(sa), "l"(gp));
        }
        asm volatile("cp.async.commit_group;");
    };

    issue_chunk(0);
    issue_chunk(1);
    issue_chunk(2);
    issue_chunk(3);

    for (int c = 0; c < NCHUNK; c++) {
        if (c + 3 < NCHUNK)      asm volatile("cp.async.wait_group 3;");
        else if (c + 2 < NCHUNK) asm volatile("cp.async.wait_group 2;");
        else if (c + 1 < NCHUNK) asm volatile("cp.async.wait_group 1;");
        else                     asm volatile("cp.async.wait_group 0;");
        __syncthreads();
        if (c + 4 < NCHUNK) issue_chunk(c + 4);

        const uint32_t* As = &sm[(c % NSTAGE) * 2560];
        const uint32_t* Bs = &sm[(NSTAGE + c % NSTAGE) * 2560];
#pragma unroll
        for (int ks = 0; ks < 2; ks++) {
            const int kk2 = ks * 8;
            uint32_t a[4][4], b[4][2];
#pragma unroll
            for (int mi = 0; mi < 4; mi++) {
                int rb = warp_m * 64 + mi * 16;
                a[mi][0] = As[(rb + g) * 20 + kk2 + tg];
                a[mi][1] = As[(rb + g + 8) * 20 + kk2 + tg];
                a[mi][2] = As[(rb + g) * 20 + kk2 + tg + 4];
                a[mi][3] = As[(rb + g + 8) * 20 + kk2 + tg + 4];
            }
#pragma unroll
            for (int ni = 0; ni < 4; ni++) {
                int nb = warp_n * 32 + ni * 8;
                b[ni][0] = Bs[(nb + g) * 20 + kk2 + tg];
                b[ni][1] = Bs[(nb + g) * 20 + kk2 + tg + 4];
            }
#pragma unroll
            for (int mi = 0; mi < 4; mi++)
#pragma unroll
                for (int ni = 0; ni < 4; ni++) {
                    asm volatile(
                        "mma.sync.aligned.m16n8k16.row.col.f32.bf16.bf16.f32 "
                        "{%0,%1,%2,%3}, {%4,%5,%6,%7}, {%8,%9}, {%0,%1,%2,%3};"
                        : "+f"(acc[mi][ni][0]), "+f"(acc[mi][ni][1]),
                          "+f"(acc[mi][ni][2]), "+f"(acc[mi][ni][3])
                        : "r"(a[mi][0]), "r"(a[mi][1]), "r"(a[mi][2]), "r"(a[mi][3]),
                          "r"(b[ni][0]), "r"(b[ni][1]));
                }
        }
        __syncthreads();
    }

    // ---- epilogue: bias + relu -> bf16x2 stores ----
#pragma unroll
    for (int mi = 0; mi < 4; mi++) {
        int rb = row0 + warp_m * 64 + mi * 16 + g;
#pragma unroll
        for (int ni = 0; ni < 4; ni++) {
            int cb = col0 + warp_n * 32 + ni * 8 + tg * 2;
            float b0 = bias[cb], b1 = bias[cb + 1];
            if (rb < N_NODES) {
                __nv_bfloat162 o = __floats2bfloat162_rn(
                    fmaxf(acc[mi][ni][0] + b0, 0.f), fmaxf(acc[mi][ni][1] + b1, 0.f));
                *(__nv_bfloat162*)(C + (size_t)rb * LDC + COFF + cb) = o;
            }
            if (rb + 8 < N_NODES) {
                __nv_bfloat162 o = __floats2bfloat162_rn(
                    fmaxf(acc[mi][ni][2] + b0, 0.f), fmaxf(acc[mi][ni][3] + b1, 0.f));
                *(__nv_bfloat162*)(C + (size_t)(rb + 8) * LDC + COFF + cb) = o;
            }
        }
    }
}

// ---------------------------------------------------------------------------
// Link prediction: sigmoid(dot(z[src], z[dst])). One warp per pair, bf16 z.
// ---------------------------------------------------------------------------
__global__ void pair_kernel(const int* __restrict__ src,
                            const int* __restrict__ dst,
                            float* __restrict__ out) {
    int p = (int)(((size_t)blockIdx.x * blockDim.x + threadIdx.x) >> 5);
    int lane = threadIdx.x & 31;
    if (p >= N_PAIRS) return;
    const uint4* zs = (const uint4*)(g_z + (size_t)src[p] * HID);
    const uint4* zd = (const uint4*)(g_z + (size_t)dst[p] * HID);
    uint4 a = zs[lane];
    uint4 b = zd[lane];
    float sum = 0.f;
    const uint32_t* ap = &a.x;
    const uint32_t* bp = &b.x;
#pragma unroll
    for (int q = 0; q < 4; q++) {
        float2 fa = __bfloat1622float2(*reinterpret_cast<const __nv_bfloat162*>(ap + q));
        float2 fb = __bfloat1622float2(*reinterpret_cast<const __nv_bfloat162*>(bp + q));
        sum += fa.x * fb.x + fa.y * fb.y;
    }
#pragma unroll
    for (int o = 16; o; o >>= 1) sum += __shfl_xor_sync(0xffffffffu, sum, o);
    if (lane == 0) out[p] = 1.0f / (1.0f + expf(-sum));
}

// ---------------------------------------------------------------------------
extern "C" void kernel_launch(void* const* d_in, const int* in_sizes, int n_in,
                              void* d_out, int out_size) {
    const float* x    = (const float*)d_in[0];
    const int*   tok  = (const int*)d_in[1];
    const float* sc   = (const float*)d_in[2];
    const int*   cat  = (const int*)d_in[3];
    const int*   eidx = (const int*)d_in[4];
    const int*   psrc = (const int*)d_in[5];
    const int*   pdst = (const int*)d_in[6];
    const float* tE   = (const float*)d_in[7];
    const float* cE   = (const float*)d_in[8];
    const float* pW   = (const float*)d_in[9];
    const float* pb   = (const float*)d_in[10];
    const float* W_l0 = (const float*)d_in[11];
    const float* b_l0 = (const float*)d_in[12];
    const float* W_r0 = (const float*)d_in[13];
    const float* W_l1 = (const float*)d_in[14];
    const float* b_l1 = (const float*)d_in[15];
    const float* W_r1 = (const float*)d_in[16];
    float* out = (float*)d_out;

    const int* esrc = eidx;
    const int* edst = eidx + N_EDGES;

    cudaFuncSetAttribute(tc_gemm<320, 512, 256>,
                         cudaFuncAttributeMaxDynamicSharedMemorySize, GEMM_SMEM_BYTES);
    cudaFuncSetAttribute(tc_gemm<512, 256, 0>,
                         cudaFuncAttributeMaxDynamicSharedMemorySize, GEMM_SMEM_BYTES);

    __nv_bfloat16 *Wt0, *Wt1, *H0, *H1, *Z;
    cudaGetSymbolAddress((void**)&Wt0, g_Wt0);
    cudaGetSymbolAddress((void**)&Wt1, g_Wt1);
    cudaGetSymbolAddress((void**)&H0, g_hcat0);
    cudaGetSymbolAddress((void**)&H1, g_hcat1);
    cudaGetSymbolAddress((void**)&Z, g_z);

    // ---- fork: s1 = CSR build, s2 = weight transposes, s0 = gwas ----
    cudaEventRecord(g_eFork, 0);
    cudaStreamWaitEvent(g_s1, g_eFork, 0);
    cudaStreamWaitEvent(g_s2, g_eFork, 0);

    gwas_kernel<<<GWAS_BLOCKS, 256>>>(x, tok, sc, cat, tE, cE, pW, pb);

    zero_deg_kernel<<<(N_NODES / 4 + 255) / 256, 256, 0, g_s1>>>();
    count_kernel<<<(N_EDGES + 255) / 256, 256, 0, g_s1>>>(edst);
    scanA_kernel<<<SCAN_BLOCKS, 1024, 0, g_s1>>>();
    scanB_kernel<<<1, 32, 0, g_s1>>>();
    scanC_kernel<<<SCAN_BLOCKS, 1024, 0, g_s1>>>();
    fill_kernel<<<(N_EDGES + 255) / 256, 256, 0, g_s1>>>(esrc, edst);
    cudaEventRecord(g_eCSR, g_s1);

    wstack_kernel<<<dim3(320 / 32, HID / 32), dim3(32, 8), 0, g_s2>>>(
        W_l0, W_r0, Wt0, 160, 320);
    cudaEventRecord(g_eW0, g_s2);
    wstack_kernel<<<dim3(512 / 32, HID / 32), dim3(32, 8), 0, g_s2>>>(
        W_l1, W_r1, Wt1, 256, 512);
    cudaEventRecord(g_eW1, g_s2);

    // ---- join + main chain on s0 ----
    cudaStreamWaitEvent(0, g_eCSR, 0);
    gather_kernel<0><<<(N_NODES + 11) / 12, 256>>>();
    cudaStreamWaitEvent(0, g_eW0, 0);
    tc_gemm<320, 512, 256><<<dim3((N_NODES + 127) / 128, 2), 256, GEMM_SMEM_BYTES>>>(
        H0, Wt0, b_l0, H1);
    gather_kernel<1><<<(N_NODES + 7) / 8, 256>>>();
    cudaStreamWaitEvent(0, g_eW1, 0);
    tc_gemm<512, 256, 0><<<dim3((N_NODES + 127) / 128, 2), 256, GEMM_SMEM_BYTES>>>(
        H1, Wt1, b_l1, Z);
    pair_kernel<<<(N_PAIRS + 7) / 8, 256>>>(psrc, pdst, out);
}

// round 13
// speedup vs baseline: 1.0319x; 1.0319x over previous
#include <cuda_runtime.h>
#include <cuda_bf16.h>
#include <cstdint>

#define N_NODES 50000
#define N_EDGES 800000
#define N_PAIRS 100000
#define IN_CH 128
#define HID 256
#define EMB 32
#define CAT_EMB 8
#define MAX_TOK 20

// bf16 rows. hcat0: [agg(160) | x(128) gwas(32)] = 320 bf16 (640 B)
//            hcat1: [agg(256) | h1(256)] = 512 bf16 (1 KB)
__device__ __align__(16) __nv_bfloat16 g_hcat0[(size_t)N_NODES * 320];
__device__ __align__(16) __nv_bfloat16 g_hcat1[(size_t)N_NODES * 512];
__device__ __align__(16) __nv_bfloat16 g_z[(size_t)N_NODES * HID];
// CSR for in-edges (dst -> list of src)
__device__ __align__(16) int g_deg[N_NODES];
__device__ int g_off[N_NODES + 1];
__device__ int g_cur[N_NODES];
__device__ int g_nbr[N_EDGES];
#define SCAN_BLOCKS 49
__device__ int g_bsum[SCAN_BLOCKS];
__device__ int g_bpre[SCAN_BLOCKS];
// stacked transposed weights, K-major bf16
__device__ __align__(16) __nv_bfloat16 g_Wt0[(size_t)HID * 320];
__device__ __align__(16) __nv_bfloat16 g_Wt1[(size_t)HID * 512];

// ---------------------------------------------------------------------------
// Streams/events for the forked launch DAG (created at program load).
// ---------------------------------------------------------------------------
static cudaStream_t g_s1, g_s2;
static cudaEvent_t g_eFork, g_eCSR, g_eW0, g_eW1;
namespace {
struct StreamInit {
    StreamInit() {
        cudaStreamCreateWithFlags(&g_s1, cudaStreamNonBlocking);
        cudaStreamCreateWithFlags(&g_s2, cudaStreamNonBlocking);
        cudaEventCreateWithFlags(&g_eFork, cudaEventDisableTiming);
        cudaEventCreateWithFlags(&g_eCSR, cudaEventDisableTiming);
        cudaEventCreateWithFlags(&g_eW0, cudaEventDisableTiming);
        cudaEventCreateWithFlags(&g_eW1, cudaEventDisableTiming);
    }
};
StreamInit g_stream_init;
}  // namespace

// ---------------------------------------------------------------------------
// GWAS encoder (one warp/node, linearity-rewritten) + concat(x) -> hcat0.
// ---------------------------------------------------------------------------
#define GWAS_BLOCKS (N_NODES / 8)

__global__ void gwas_kernel(const float* __restrict__ x,
                            const int* __restrict__ tok,
                            const float* __restrict__ sc,
                            const int* __restrict__ cat,
                            const float* __restrict__ tE,
                            const float* __restrict__ cE,
                            const float* __restrict__ pW,
                            const float* __restrict__ pb) {
    int node = (int)(((size_t)blockIdx.x * blockDim.x + threadIdx.x) >> 5);
    int lane = threadIdx.x & 31;
    if (node >= N_NODES) return;

    float4 xv = ((const float4*)(x + (size_t)node * IN_CH))[lane];
    uint2 xp;
    {
        __nv_bfloat162 lo = __floats2bfloat162_rn(xv.x, xv.y);
        __nv_bfloat162 hi = __floats2bfloat162_rn(xv.z, xv.w);
        xp.x = *reinterpret_cast<uint32_t*>(&lo);
        xp.y = *reinterpret_cast<uint32_t*>(&hi);
    }
    *(uint2*)(g_hcat0 + (size_t)node * 320 + 160 + 4 * lane) = xp;

    float ts = 0.f, cs = 0.f, ssum = 0.f, wsum = 0.f;
#pragma unroll 4
    for (int t = 0; t < MAX_TOK; t++) {
        int id  = tok[(size_t)node * MAX_TOK + t];
        float s = sc[(size_t)node * MAX_TOK + t];
        int cid = cat[(size_t)node * MAX_TOK + t];
        float te = tE[(size_t)id * EMB + lane];
        float ce = (lane < CAT_EMB) ? cE[cid * CAT_EMB + lane] : 0.f;
        float wt = (id != 0) ? s : 0.f;
        ts += wt * te;
        cs += wt * ce;
        ssum += wt * s;
        wsum += wt;
    }

    float w[41];
#pragma unroll
    for (int k = 0; k < 41; k++) w[k] = pW[k * EMB + lane];
    float acc = wsum * pb[lane] + ssum * w[40];
#pragma unroll
    for (int k = 0; k < 32; k++)
        acc += __shfl_sync(0xffffffffu, ts, k) * w[k];
#pragma unroll
    for (int k = 0; k < 8; k++)
        acc += __shfl_sync(0xffffffffu, cs, k) * w[32 + k];

    g_hcat0[(size_t)node * 320 + 288 + lane] =
        __float2bfloat16(acc / fmaxf(wsum, 1e-8f));
}

// ---------------------------------------------------------------------------
// CSR build: zero -> count -> two-level scan (A/B/C) -> fill
// ---------------------------------------------------------------------------
__global__ void zero_deg_kernel() {
    int i = blockIdx.x * blockDim.x + threadIdx.x;
    if (i < N_NODES / 4) ((uint4*)g_deg)[i] = make_uint4(0, 0, 0, 0);
}

__global__ void count_kernel(const int* __restrict__ edst) {
    int i = blockIdx.x * blockDim.x + threadIdx.x;
    if (i < N_EDGES) atomicAdd(&g_deg[edst[i]], 1);
}

__global__ void __launch_bounds__(1024, 1) scanA_kernel() {
    __shared__ int wsum[32];
    int tid = threadIdx.x, lane = tid & 31, w = tid >> 5;
    int i = blockIdx.x * 1024 + tid;
    int v = (i < N_NODES) ? g_deg[i] : 0;
    int xx = v;
#pragma unroll
    for (int o = 1; o < 32; o <<= 1) {
        int t = __shfl_up_sync(0xffffffffu, xx, o);
        if (lane >= o) xx += t;
    }
    if (lane == 31) wsum[w] = xx;
    __syncthreads();
    if (w == 0) {
        int s = wsum[lane];
#pragma unroll
        for (int o = 1; o < 32; o <<= 1) {
            int t = __shfl_up_sync(0xffffffffu, s, o);
            if (lane >= o) s += t;
        }
        wsum[lane] = s;
    }
    __syncthreads();
    int incl = xx + ((w > 0) ? wsum[w - 1] : 0);
    if (i < N_NODES) g_cur[i] = incl - v;           // exclusive within block
    if (tid == 1023) g_bsum[blockIdx.x] = incl;     // block total
}

__global__ void scanB_kernel() {
    int lane = threadIdx.x;
    int v0 = (lane < SCAN_BLOCKS) ? g_bsum[lane] : 0;
    int v1 = (32 + lane < SCAN_BLOCKS) ? g_bsum[32 + lane] : 0;
    int x0 = v0;
#pragma unroll
    for (int o = 1; o < 32; o <<= 1) {
        int t = __shfl_up_sync(0xffffffffu, x0, o);
        if (lane >= o) x0 += t;
    }
    int tot0 = __shfl_sync(0xffffffffu, x0, 31);
    int x1 = v1;
#pragma unroll
    for (int o = 1; o < 32; o <<= 1) {
        int t = __shfl_up_sync(0xffffffffu, x1, o);
        if (lane >= o) x1 += t;
    }
    if (lane < SCAN_BLOCKS) g_bpre[lane] = x0 - v0;
    if (32 + lane < SCAN_BLOCKS) g_bpre[32 + lane] = tot0 + x1 - v1;
    if (lane == SCAN_BLOCKS - 32 - 1)
        g_off[N_NODES] = tot0 + x1;
}

__global__ void __launch_bounds__(1024, 1) scanC_kernel() {
    int i = blockIdx.x * 1024 + threadIdx.x;
    if (i < N_NODES) {
        int e = g_cur[i] + g_bpre[blockIdx.x];
        g_off[i] = e;
        g_cur[i] = e;
    }
}

__global__ void fill_kernel(const int* __restrict__ esrc,
                            const int* __restrict__ edst) {
    int i = blockIdx.x * blockDim.x + threadIdx.x;
    if (i < N_EDGES) {
        int p = atomicAdd(&g_cur[edst[i]], 1);
        g_nbr[p] = esrc[i];
    }
}

// ---------------------------------------------------------------------------
// Stack + transpose weights into K-major bf16 [HID, K].
// ---------------------------------------------------------------------------
__global__ void wstack_kernel(const float* __restrict__ Wl,
                              const float* __restrict__ Wr,
                              __nv_bfloat16* __restrict__ out, int K1, int K) {
    __shared__ float t[32][33];
    int kb = blockIdx.x * 32, nb = blockIdx.y * 32;
    for (int dy = threadIdx.y; dy < 32; dy += 8) {
        int k = kb + dy, n = nb + threadIdx.x;
        t[dy][threadIdx.x] = (k < K1) ? Wl[(size_t)k * HID + n]
                                      : Wr[(size_t)(k - K1) * HID + n];
    }
    __syncthreads();
    for (int dy = threadIdx.y; dy < 32; dy += 8) {
        int n = nb + dy, k = kb + threadIdx.x;
        out[(size_t)n * K + k] = __float2bfloat16(t[threadIdx.x][dy]);
    }
}

// ---------------------------------------------------------------------------
// CSR gather-aggregate (R9 form — simple loop, TLP-saturated):
// mean of in-neighbor feature halves, bf16x2 adds, fp32 normalize once.
// Layer0: 320-thread blocks (16 nodes x 20 chunks, all lanes active).
// Layer1: 256-thread blocks (8 nodes x 32 chunks).
// ---------------------------------------------------------------------------
template <int LAYER>
__global__ void gather_kernel() {
    constexpr int CHUNKS = (LAYER == 0) ? 20 : 32;
    constexpr int NTHR   = (LAYER == 0) ? 320 : 256;
    constexpr int EPB    = NTHR / CHUNKS;
    constexpr int ROWE   = (LAYER == 0) ? 320 : 512;
    constexpr int FOFF   = (LAYER == 0) ? 160 : 256;
    __nv_bfloat16* base = (LAYER == 0) ? g_hcat0 : g_hcat1;

    int tid = threadIdx.x;
    int el = tid / CHUNKS;
    int q  = tid - el * CHUNKS;
    if (el >= EPB) return;
    int n = blockIdx.x * EPB + el;
    if (n >= N_NODES) return;

    int beg = g_off[n], end = g_off[n + 1];
    __nv_bfloat162 a0 = __floats2bfloat162_rn(0.f, 0.f);
    __nv_bfloat162 a1 = a0, a2 = a0, a3 = a0;
    for (int j = beg; j < end; j++) {
        int s = g_nbr[j];
        uint4 v = *(const uint4*)(base + (size_t)s * ROWE + FOFF + 8 * q);
        a0 = __hadd2(a0, *reinterpret_cast<__nv_bfloat162*>(&v.x));
        a1 = __hadd2(a1, *reinterpret_cast<__nv_bfloat162*>(&v.y));
        a2 = __hadd2(a2, *reinterpret_cast<__nv_bfloat162*>(&v.z));
        a3 = __hadd2(a3, *reinterpret_cast<__nv_bfloat162*>(&v.w));
    }
    int d = end - beg;
    float rv = 1.f / (float)((d > 1) ? d : 1);
    uint4 o;
    {
        float2 f;
        __nv_bfloat162 r;
        f = __bfloat1622float2(a0); r = __floats2bfloat162_rn(f.x * rv, f.y * rv);
        o.x = *reinterpret_cast<uint32_t*>(&r);
        f = __bfloat1622float2(a1); r = __floats2bfloat162_rn(f.x * rv, f.y * rv);
        o.y = *reinterpret_cast<uint32_t*>(&r);
        f = __bfloat1622float2(a2); r = __floats2bfloat162_rn(f.x * rv, f.y * rv);
        o.z = *reinterpret_cast<uint32_t*>(&r);
        f = __bfloat1622float2(a3); r = __floats2bfloat162_rn(f.x * rv, f.y * rv);
        o.w = *reinterpret_cast<uint32_t*>(&r);
    }
    *(uint4*)(base + (size_t)n * ROWE + 8 * q) = o;
}

// ---------------------------------------------------------------------------
// bf16 mma.sync GEMM, 5-stage cp.async pipeline (dynamic smem, 100 KB).
// BM=128 BN=128 BK=32, 256 threads (8 warps 2x4), warp tile 64x32, m16n8k16.
// (R9-exact: two barriers per chunk iteration.)
// ---------------------------------------------------------------------------
#define NSTAGE 5
#define GEMM_SMEM_BYTES (2 * NSTAGE * 2560 * 4)

template <int KTOT, int LDC, int COFF>
__global__ void __launch_bounds__(256, 2)
tc_gemm(const __nv_bfloat16* __restrict__ A, const __nv_bfloat16* __restrict__ Bt,
        const float* __restrict__ bias, __nv_bfloat16* __restrict__ C) {
    extern __shared__ uint32_t sm[];
    const int tid = threadIdx.x;
    const int wid = tid >> 5, lane = tid & 31;
    const int g = lane >> 2, tg = lane & 3;
    const int warp_m = wid >> 2, warp_n = wid & 3;
    const int row0 = blockIdx.x * 128;
    const int col0 = blockIdx.y * 128;

    float acc[4][4][4];
#pragma unroll
    for (int mi = 0; mi < 4; mi++)
#pragma unroll
        for (int ni = 0; ni < 4; ni++)
#pragma unroll
            for (int q = 0; q < 4; q++) acc[mi][ni][q] = 0.f;

    constexpr int NCHUNK = KTOT / 32;

    auto issue_chunk = [&](int c) {
        int st = c % NSTAGE;
        int k0 = c * 32;
#pragma unroll
        for (int i = 0; i < 2; i++) {
            int idx = tid + i * 256;
            int r = idx >> 2, c4 = idx & 3;
            int gr = row0 + r;
            int grc = (gr < N_NODES) ? gr : (N_NODES - 1);
            const __nv_bfloat16* gp = A + (size_t)grc * KTOT + k0 + c4 * 8;
            uint32_t sa = (uint32_t)__cvta_generic_to_shared(
                &sm[st * 2560 + r * 20 + c4 * 4]);
            int sz = (gr < N_NODES) ? 16 : 0;
            asm volatile("cp.async.cg.shared.global [%0], [%1], 16, %2;"
                         :: "r"(sa), "l"(gp), "r"(sz));
        }
#pragma unroll
        for (int i = 0; i < 2; i++) {
            int idx = tid + i * 256;
            int n = idx >> 2, c4 = idx & 3;
            const __nv_bfloat16* gp = Bt + (size_t)(col0 + n) * KTOT + k0 + c4 * 8;
            uint32_t sa = (uint32_t)__cvta_generic_to_shared(
                &sm[(NSTAGE + st) * 2560 + n * 20 + c4 * 4]);
            asm volatile("cp.async.cg.shared.global [%0], [%1], 16;"
                         :: "r"(sa), "l"(gp));
        }
        asm volatile("cp.async.commit_group;");
    };

    issue_chunk(0);
    issue_chunk(1);
    issue_chunk(2);
    issue_chunk(3);

    for (int c = 0; c < NCHUNK; c++) {
        if (c + 3 < NCHUNK)      asm volatile("cp.async.wait_group 3;");
        else if (c + 2 < NCHUNK) asm volatile("cp.async.wait_group 2;");
        else if (c + 1 < NCHUNK) asm volatile("cp.async.wait_group 1;");
        else                     asm volatile("cp.async.wait_group 0;");
        __syncthreads();
        if (c + 4 < NCHUNK) issue_chunk(c + 4);

        const uint32_t* As = &sm[(c % NSTAGE) * 2560];
        const uint32_t* Bs = &sm[(NSTAGE + c % NSTAGE) * 2560];
#pragma unroll
        for (int ks = 0; ks < 2; ks++) {
            const int kk2 = ks * 8;
            uint32_t a[4][4], b[4][2];
#pragma unroll
            for (int mi = 0; mi < 4; mi++) {
                int rb = warp_m * 64 + mi * 16;
                a[mi][0] = As[(rb + g) * 20 + kk2 + tg];
                a[mi][1] = As[(rb + g + 8) * 20 + kk2 + tg];
                a[mi][2] = As[(rb + g) * 20 + kk2 + tg + 4];
                a[mi][3] = As[(rb + g + 8) * 20 + kk2 + tg + 4];
            }
#pragma unroll
            for (int ni = 0; ni < 4; ni++) {
                int nb = warp_n * 32 + ni * 8;
                b[ni][0] = Bs[(nb + g) * 20 + kk2 + tg];
                b[ni][1] = Bs[(nb + g) * 20 + kk2 + tg + 4];
            }
#pragma unroll
            for (int mi = 0; mi < 4; mi++)
#pragma unroll
                for (int ni = 0; ni < 4; ni++) {
                    asm volatile(
                        "mma.sync.aligned.m16n8k16.row.col.f32.bf16.bf16.f32 "
                        "{%0,%1,%2,%3}, {%4,%5,%6,%7}, {%8,%9}, {%0,%1,%2,%3};"
                        : "+f"(acc[mi][ni][0]), "+f"(acc[mi][ni][1]),
                          "+f"(acc[mi][ni][2]), "+f"(acc[mi][ni][3])
                        : "r"(a[mi][0]), "r"(a[mi][1]), "r"(a[mi][2]), "r"(a[mi][3]),
                          "r"(b[ni][0]), "r"(b[ni][1]));
                }
        }
        __syncthreads();
    }

    // ---- epilogue: bias + relu -> bf16x2 stores ----
#pragma unroll
    for (int mi = 0; mi < 4; mi++) {
        int rb = row0 + warp_m * 64 + mi * 16 + g;
#pragma unroll
        for (int ni = 0; ni < 4; ni++) {
            int cb = col0 + warp_n * 32 + ni * 8 + tg * 2;
            float b0 = bias[cb], b1 = bias[cb + 1];
            if (rb < N_NODES) {
                __nv_bfloat162 o = __floats2bfloat162_rn(
                    fmaxf(acc[mi][ni][0] + b0, 0.f), fmaxf(acc[mi][ni][1] + b1, 0.f));
                *(__nv_bfloat162*)(C + (size_t)rb * LDC + COFF + cb) = o;
            }
            if (rb + 8 < N_NODES) {
                __nv_bfloat162 o = __floats2bfloat162_rn(
                    fmaxf(acc[mi][ni][2] + b0, 0.f), fmaxf(acc[mi][ni][3] + b1, 0.f));
                *(__nv_bfloat162*)(C + (size_t)(rb + 8) * LDC + COFF + cb) = o;
            }
        }
    }
}

// ---------------------------------------------------------------------------
// Link prediction: sigmoid(dot(z[src], z[dst])). One warp per pair, bf16 z.
// ---------------------------------------------------------------------------
__global__ void pair_kernel(const int* __restrict__ src,
                            const int* __restrict__ dst,
                            float* __restrict__ out) {
    int p = (int)(((size_t)blockIdx.x * blockDim.x + threadIdx.x) >> 5);
    int lane = threadIdx.x & 31;
    if (p >= N_PAIRS) return;
    const uint4* zs = (const uint4*)(g_z + (size_t)src[p] * HID);
    const uint4* zd = (const uint4*)(g_z + (size_t)dst[p] * HID);
    uint4 a = zs[lane];
    uint4 b = zd[lane];
    float sum = 0.f;
    const uint32_t* ap = &a.x;
    const uint32_t* bp = &b.x;
#pragma unroll
    for (int q = 0; q < 4; q++) {
        float2 fa = __bfloat1622float2(*reinterpret_cast<const __nv_bfloat162*>(ap + q));
        float2 fb = __bfloat1622float2(*reinterpret_cast<const __nv_bfloat162*>(bp + q));
        sum += fa.x * fb.x + fa.y * fb.y;
    }
#pragma unroll
    for (int o = 16; o; o >>= 1) sum += __shfl_xor_sync(0xffffffffu, sum, o);
    if (lane == 0) out[p] = 1.0f / (1.0f + expf(-sum));
}

// ---------------------------------------------------------------------------
extern "C" void kernel_launch(void* const* d_in, const int* in_sizes, int n_in,
                              void* d_out, int out_size) {
    const float* x    = (const float*)d_in[0];
    const int*   tok  = (const int*)d_in[1];
    const float* sc   = (const float*)d_in[2];
    const int*   cat  = (const int*)d_in[3];
    const int*   eidx = (const int*)d_in[4];
    const int*   psrc = (const int*)d_in[5];
    const int*   pdst = (const int*)d_in[6];
    const float* tE   = (const float*)d_in[7];
    const float* cE   = (const float*)d_in[8];
    const float* pW   = (const float*)d_in[9];
    const float* pb   = (const float*)d_in[10];
    const float* W_l0 = (const float*)d_in[11];
    const float* b_l0 = (const float*)d_in[12];
    const float* W_r0 = (const float*)d_in[13];
    const float* W_l1 = (const float*)d_in[14];
    const float* b_l1 = (const float*)d_in[15];
    const float* W_r1 = (const float*)d_in[16];
    float* out = (float*)d_out;

    const int* esrc = eidx;
    const int* edst = eidx + N_EDGES;

    cudaFuncSetAttribute(tc_gemm<320, 512, 256>,
                         cudaFuncAttributeMaxDynamicSharedMemorySize, GEMM_SMEM_BYTES);
    cudaFuncSetAttribute(tc_gemm<512, 256, 0>,
                         cudaFuncAttributeMaxDynamicSharedMemorySize, GEMM_SMEM_BYTES);

    __nv_bfloat16 *Wt0, *Wt1, *H0, *H1, *Z;
    cudaGetSymbolAddress((void**)&Wt0, g_Wt0);
    cudaGetSymbolAddress((void**)&Wt1, g_Wt1);
    cudaGetSymbolAddress((void**)&H0, g_hcat0);
    cudaGetSymbolAddress((void**)&H1, g_hcat1);
    cudaGetSymbolAddress((void**)&Z, g_z);

    // ---- fork: s1 = CSR build, s2 = weight transposes, s0 = gwas ----
    cudaEventRecord(g_eFork, 0);
    cudaStreamWaitEvent(g_s1, g_eFork, 0);
    cudaStreamWaitEvent(g_s2, g_eFork, 0);

    gwas_kernel<<<GWAS_BLOCKS, 256>>>(x, tok, sc, cat, tE, cE, pW, pb);

    zero_deg_kernel<<<(N_NODES / 4 + 255) / 256, 256, 0, g_s1>>>();
    count_kernel<<<(N_EDGES + 255) / 256, 256, 0, g_s1>>>(edst);
    scanA_kernel<<<SCAN_BLOCKS, 1024, 0, g_s1>>>();
    scanB_kernel<<<1, 32, 0, g_s1>>>();
    scanC_kernel<<<SCAN_BLOCKS, 1024, 0, g_s1>>>();
    fill_kernel<<<(N_EDGES + 255) / 256, 256, 0, g_s1>>>(esrc, edst);
    cudaEventRecord(g_eCSR, g_s1);

    wstack_kernel<<<dim3(320 / 32, HID / 32), dim3(32, 8), 0, g_s2>>>(
        W_l0, W_r0, Wt0, 160, 320);
    cudaEventRecord(g_eW0, g_s2);
    wstack_kernel<<<dim3(512 / 32, HID / 32), dim3(32, 8), 0, g_s2>>>(
        W_l1, W_r1, Wt1, 256, 512);
    cudaEventRecord(g_eW1, g_s2);

    // ---- join + main chain on s0 ----
    cudaStreamWaitEvent(0, g_eCSR, 0);
    gather_kernel<0><<<(N_NODES + 15) / 16, 320>>>();
    cudaStreamWaitEvent(0, g_eW0, 0);
    tc_gemm<320, 512, 256><<<dim3((N_NODES + 127) / 128, 2), 256, GEMM_SMEM_BYTES>>>(
        H0, Wt0, b_l0, H1);
    gather_kernel<1><<<(N_NODES + 7) / 8, 256>>>();
    cudaStreamWaitEvent(0, g_eW1, 0);
    tc_gemm<512, 256, 0><<<dim3((N_NODES + 127) / 128, 2), 256, GEMM_SMEM_BYTES>>>(
        H1, Wt1, b_l1, Z);
    pair_kernel<<<(N_PAIRS + 7) / 8, 256>>>(psrc, pdst, out);
}

// round 14
// speedup vs baseline: 1.0638x; 1.0309x over previous
#include <cuda_runtime.h>
#include <cuda_bf16.h>
#include <cstdint>

#define N_NODES 50000
#define N_EDGES 800000
#define N_PAIRS 100000
#define IN_CH 128
#define HID 256
#define EMB 32
#define CAT_EMB 8
#define MAX_TOK 20

// row split: half A = rows [0, 25088) = 196 tiles, half B = rest (195 tiles)
#define SPLIT_NODE 25088
#define TILES_A 196
#define TILES_B 195

// bf16 rows. hcat0: [agg(160) | x(128) gwas(32)] = 320 bf16 (640 B)
//            hcat1: [agg(256) | h1(256)] = 512 bf16 (1 KB)
__device__ __align__(16) __nv_bfloat16 g_hcat0[(size_t)N_NODES * 320];
__device__ __align__(16) __nv_bfloat16 g_hcat1[(size_t)N_NODES * 512];
__device__ __align__(16) __nv_bfloat16 g_z[(size_t)N_NODES * HID];
// CSR for in-edges (dst -> list of src)
__device__ __align__(16) int g_deg[N_NODES];
__device__ int g_off[N_NODES + 1];
__device__ int g_cur[N_NODES];
__device__ int g_nbr[N_EDGES];
#define SCAN_BLOCKS 49
__device__ int g_bsum[SCAN_BLOCKS];
__device__ int g_bpre[SCAN_BLOCKS];
// stacked transposed weights, K-major bf16
__device__ __align__(16) __nv_bfloat16 g_Wt0[(size_t)HID * 320];
__device__ __align__(16) __nv_bfloat16 g_Wt1[(size_t)HID * 512];

// ---------------------------------------------------------------------------
// Streams/events for the pipelined launch DAG (created at program load).
// ---------------------------------------------------------------------------
static cudaStream_t g_s1, g_s2;
static cudaEvent_t g_eFork, g_eCSR, g_eW0, g_eW1, g_eGwas, g_eM0A, g_eM0B, g_eM1B;
namespace {
struct StreamInit {
    StreamInit() {
        cudaStreamCreateWithFlags(&g_s1, cudaStreamNonBlocking);
        cudaStreamCreateWithFlags(&g_s2, cudaStreamNonBlocking);
        cudaEventCreateWithFlags(&g_eFork, cudaEventDisableTiming);
        cudaEventCreateWithFlags(&g_eCSR, cudaEventDisableTiming);
        cudaEventCreateWithFlags(&g_eW0, cudaEventDisableTiming);
        cudaEventCreateWithFlags(&g_eW1, cudaEventDisableTiming);
        cudaEventCreateWithFlags(&g_eGwas, cudaEventDisableTiming);
        cudaEventCreateWithFlags(&g_eM0A, cudaEventDisableTiming);
        cudaEventCreateWithFlags(&g_eM0B, cudaEventDisableTiming);
        cudaEventCreateWithFlags(&g_eM1B, cudaEventDisableTiming);
    }
};
StreamInit g_stream_init;
}  // namespace

// ---------------------------------------------------------------------------
// GWAS encoder (one warp/node, linearity-rewritten) + concat(x) -> hcat0.
// ---------------------------------------------------------------------------
#define GWAS_BLOCKS (N_NODES / 8)

__global__ void gwas_kernel(const float* __restrict__ x,
                            const int* __restrict__ tok,
                            const float* __restrict__ sc,
                            const int* __restrict__ cat,
                            const float* __restrict__ tE,
                            const float* __restrict__ cE,
                            const float* __restrict__ pW,
                            const float* __restrict__ pb) {
    int node = (int)(((size_t)blockIdx.x * blockDim.x + threadIdx.x) >> 5);
    int lane = threadIdx.x & 31;
    if (node >= N_NODES) return;

    float4 xv = ((const float4*)(x + (size_t)node * IN_CH))[lane];
    uint2 xp;
    {
        __nv_bfloat162 lo = __floats2bfloat162_rn(xv.x, xv.y);
        __nv_bfloat162 hi = __floats2bfloat162_rn(xv.z, xv.w);
        xp.x = *reinterpret_cast<uint32_t*>(&lo);
        xp.y = *reinterpret_cast<uint32_t*>(&hi);
    }
    *(uint2*)(g_hcat0 + (size_t)node * 320 + 160 + 4 * lane) = xp;

    float ts = 0.f, cs = 0.f, ssum = 0.f, wsum = 0.f;
#pragma unroll 4
    for (int t = 0; t < MAX_TOK; t++) {
        int id  = tok[(size_t)node * MAX_TOK + t];
        float s = sc[(size_t)node * MAX_TOK + t];
        int cid = cat[(size_t)node * MAX_TOK + t];
        float te = tE[(size_t)id * EMB + lane];
        float ce = (lane < CAT_EMB) ? cE[cid * CAT_EMB + lane] : 0.f;
        float wt = (id != 0) ? s : 0.f;
        ts += wt * te;
        cs += wt * ce;
        ssum += wt * s;
        wsum += wt;
    }

    float w[41];
#pragma unroll
    for (int k = 0; k < 41; k++) w[k] = pW[k * EMB + lane];
    float acc = wsum * pb[lane] + ssum * w[40];
#pragma unroll
    for (int k = 0; k < 32; k++)
        acc += __shfl_sync(0xffffffffu, ts, k) * w[k];
#pragma unroll
    for (int k = 0; k < 8; k++)
        acc += __shfl_sync(0xffffffffu, cs, k) * w[32 + k];

    g_hcat0[(size_t)node * 320 + 288 + lane] =
        __float2bfloat16(acc / fmaxf(wsum, 1e-8f));
}

// ---------------------------------------------------------------------------
// CSR build: zero -> count -> two-level scan (A/B/C) -> fill
// ---------------------------------------------------------------------------
__global__ void zero_deg_kernel() {
    int i = blockIdx.x * blockDim.x + threadIdx.x;
    if (i < N_NODES / 4) ((uint4*)g_deg)[i] = make_uint4(0, 0, 0, 0);
}

__global__ void count_kernel(const int* __restrict__ edst) {
    int i = blockIdx.x * blockDim.x + threadIdx.x;
    if (i < N_EDGES) atomicAdd(&g_deg[edst[i]], 1);
}

__global__ void __launch_bounds__(1024, 1) scanA_kernel() {
    __shared__ int wsum[32];
    int tid = threadIdx.x, lane = tid & 31, w = tid >> 5;
    int i = blockIdx.x * 1024 + tid;
    int v = (i < N_NODES) ? g_deg[i] : 0;
    int xx = v;
#pragma unroll
    for (int o = 1; o < 32; o <<= 1) {
        int t = __shfl_up_sync(0xffffffffu, xx, o);
        if (lane >= o) xx += t;
    }
    if (lane == 31) wsum[w] = xx;
    __syncthreads();
    if (w == 0) {
        int s = wsum[lane];
#pragma unroll
        for (int o = 1; o < 32; o <<= 1) {
            int t = __shfl_up_sync(0xffffffffu, s, o);
            if (lane >= o) s += t;
        }
        wsum[lane] = s;
    }
    __syncthreads();
    int incl = xx + ((w > 0) ? wsum[w - 1] : 0);
    if (i < N_NODES) g_cur[i] = incl - v;           // exclusive within block
    if (tid == 1023) g_bsum[blockIdx.x] = incl;     // block total
}

__global__ void scanB_kernel() {
    int lane = threadIdx.x;
    int v0 = (lane < SCAN_BLOCKS) ? g_bsum[lane] : 0;
    int v1 = (32 + lane < SCAN_BLOCKS) ? g_bsum[32 + lane] : 0;
    int x0 = v0;
#pragma unroll
    for (int o = 1; o < 32; o <<= 1) {
        int t = __shfl_up_sync(0xffffffffu, x0, o);
        if (lane >= o) x0 += t;
    }
    int tot0 = __shfl_sync(0xffffffffu, x0, 31);
    int x1 = v1;
#pragma unroll
    for (int o = 1; o < 32; o <<= 1) {
        int t = __shfl_up_sync(0xffffffffu, x1, o);
        if (lane >= o) x1 += t;
    }
    if (lane < SCAN_BLOCKS) g_bpre[lane] = x0 - v0;
    if (32 + lane < SCAN_BLOCKS) g_bpre[32 + lane] = tot0 + x1 - v1;
    if (lane == SCAN_BLOCKS - 32 - 1)
        g_off[N_NODES] = tot0 + x1;
}

__global__ void __launch_bounds__(1024, 1) scanC_kernel() {
    int i = blockIdx.x * 1024 + threadIdx.x;
    if (i < N_NODES) {
        int e = g_cur[i] + g_bpre[blockIdx.x];
        g_off[i] = e;
        g_cur[i] = e;
    }
}

__global__ void fill_kernel(const int* __restrict__ esrc,
                            const int* __restrict__ edst) {
    int i = blockIdx.x * blockDim.x + threadIdx.x;
    if (i < N_EDGES) {
        int p = atomicAdd(&g_cur[edst[i]], 1);
        g_nbr[p] = esrc[i];
    }
}

// ---------------------------------------------------------------------------
// Stack + transpose weights into K-major bf16 [HID, K].
// ---------------------------------------------------------------------------
__global__ void wstack_kernel(const float* __restrict__ Wl,
                              const float* __restrict__ Wr,
                              __nv_bfloat16* __restrict__ out, int K1, int K) {
    __shared__ float t[32][33];
    int kb = blockIdx.x * 32, nb = blockIdx.y * 32;
    for (int dy = threadIdx.y; dy < 32; dy += 8) {
        int k = kb + dy, n = nb + threadIdx.x;
        t[dy][threadIdx.x] = (k < K1) ? Wl[(size_t)k * HID + n]
                                      : Wr[(size_t)(k - K1) * HID + n];
    }
    __syncthreads();
    for (int dy = threadIdx.y; dy < 32; dy += 8) {
        int n = nb + dy, k = kb + threadIdx.x;
        out[(size_t)n * K + k] = __float2bfloat16(t[threadIdx.x][dy]);
    }
}

// ---------------------------------------------------------------------------
// CSR gather-aggregate over a node range [nbase, nend):
// mean of in-neighbor feature halves, bf16x2 adds, fp32 normalize once.
// ---------------------------------------------------------------------------
template <int LAYER>
__global__ void gather_kernel(int nbase, int nend) {
    constexpr int CHUNKS = (LAYER == 0) ? 20 : 32;
    constexpr int EPB    = 256 / CHUNKS;
    constexpr int ROWE   = (LAYER == 0) ? 320 : 512;
    constexpr int FOFF   = (LAYER == 0) ? 160 : 256;
    __nv_bfloat16* base = (LAYER == 0) ? g_hcat0 : g_hcat1;

    int tid = threadIdx.x;
    int el = tid / CHUNKS;
    int q  = tid - el * CHUNKS;
    if (el >= EPB) return;
    int n = nbase + blockIdx.x * EPB + el;
    if (n >= nend) return;

    int beg = g_off[n], end = g_off[n + 1];
    __nv_bfloat162 a0 = __floats2bfloat162_rn(0.f, 0.f);
    __nv_bfloat162 a1 = a0, a2 = a0, a3 = a0;
    for (int j = beg; j < end; j++) {
        int s = g_nbr[j];
        uint4 v = *(const uint4*)(base + (size_t)s * ROWE + FOFF + 8 * q);
        a0 = __hadd2(a0, *reinterpret_cast<__nv_bfloat162*>(&v.x));
        a1 = __hadd2(a1, *reinterpret_cast<__nv_bfloat162*>(&v.y));
        a2 = __hadd2(a2, *reinterpret_cast<__nv_bfloat162*>(&v.z));
        a3 = __hadd2(a3, *reinterpret_cast<__nv_bfloat162*>(&v.w));
    }
    int d = end - beg;
    float rv = 1.f / (float)((d > 1) ? d : 1);
    uint4 o;
    {
        float2 f;
        __nv_bfloat162 r;
        f = __bfloat1622float2(a0); r = __floats2bfloat162_rn(f.x * rv, f.y * rv);
        o.x = *reinterpret_cast<uint32_t*>(&r);
        f = __bfloat1622float2(a1); r = __floats2bfloat162_rn(f.x * rv, f.y * rv);
        o.y = *reinterpret_cast<uint32_t*>(&r);
        f = __bfloat1622float2(a2); r = __floats2bfloat162_rn(f.x * rv, f.y * rv);
        o.z = *reinterpret_cast<uint32_t*>(&r);
        f = __bfloat1622float2(a3); r = __floats2bfloat162_rn(f.x * rv, f.y * rv);
        o.w = *reinterpret_cast<uint32_t*>(&r);
    }
    *(uint4*)(base + (size_t)n * ROWE + 8 * q) = o;
}

// ---------------------------------------------------------------------------
// bf16 mma.sync GEMM over a row-tile range, 5-stage cp.async pipeline.
// BM=128 BN=128 BK=32, 256 threads (8 warps 2x4), warp tile 64x32, m16n8k16.
// tile_base shifts blockIdx.x so halves can run on different streams.
// ---------------------------------------------------------------------------
#define NSTAGE 5
#define GEMM_SMEM_BYTES (2 * NSTAGE * 2560 * 4)

template <int KTOT, int LDC, int COFF>
__global__ void __launch_bounds__(256, 2)
tc_gemm(const __nv_bfloat16* __restrict__ A, const __nv_bfloat16* __restrict__ Bt,
        const float* __restrict__ bias, __nv_bfloat16* __restrict__ C,
        int tile_base) {
    extern __shared__ uint32_t sm[];
    const int tid = threadIdx.x;
    const int wid = tid >> 5, lane = tid & 31;
    const int g = lane >> 2, tg = lane & 3;
    const int warp_m = wid >> 2, warp_n = wid & 3;
    const int row0 = (blockIdx.x + tile_base) * 128;
    const int col0 = blockIdx.y * 128;

    float acc[4][4][4];
#pragma unroll
    for (int mi = 0; mi < 4; mi++)
#pragma unroll
        for (int ni = 0; ni < 4; ni++)
#pragma unroll
            for (int q = 0; q < 4; q++) acc[mi][ni][q] = 0.f;

    constexpr int NCHUNK = KTOT / 32;

    auto issue_chunk = [&](int c) {
        int st = c % NSTAGE;
        int k0 = c * 32;
#pragma unroll
        for (int i = 0; i < 2; i++) {
            int idx = tid + i * 256;
            int r = idx >> 2, c4 = idx & 3;
            int gr = row0 + r;
            int grc = (gr < N_NODES) ? gr : (N_NODES - 1);
            const __nv_bfloat16* gp = A + (size_t)grc * KTOT + k0 + c4 * 8;
            uint32_t sa = (uint32_t)__cvta_generic_to_shared(
                &sm[st * 2560 + r * 20 + c4 * 4]);
            int sz = (gr < N_NODES) ? 16 : 0;
            asm volatile("cp.async.cg.shared.global [%0], [%1], 16, %2;"
                         :: "r"(sa), "l"(gp), "r"(sz));
        }
#pragma unroll
        for (int i = 0; i < 2; i++) {
            int idx = tid + i * 256;
            int n = idx >> 2, c4 = idx & 3;
            const __nv_bfloat16* gp = Bt + (size_t)(col0 + n) * KTOT + k0 + c4 * 8;
            uint32_t sa = (uint32_t)__cvta_generic_to_shared(
                &sm[(NSTAGE + st) * 2560 + n * 20 + c4 * 4]);
            asm volatile("cp.async.cg.shared.global [%0], [%1], 16;"
                         :: "r"(sa), "l"(gp));
        }
        asm volatile("cp.async.commit_group;");
    };

    issue_chunk(0);
    issue_chunk(1);
    issue_chunk(2);
    issue_chunk(3);

    for (int c = 0; c < NCHUNK; c++) {
        if (c + 3 < NCHUNK)      asm volatile("cp.async.wait_group 3;");
        else if (c + 2 < NCHUNK) asm volatile("cp.async.wait_group 2;");
        else if (c + 1 < NCHUNK) asm volatile("cp.async.wait_group 1;");
        else                     asm volatile("cp.async.wait_group 0;");
        __syncthreads();
        if (c + 4 < NCHUNK) issue_chunk(c + 4);

        const uint32_t* As = &sm[(c % NSTAGE) * 2560];
        const uint32_t* Bs = &sm[(NSTAGE + c % NSTAGE) * 2560];
#pragma unroll
        for (int ks = 0; ks < 2; ks++) {
            const int kk2 = ks * 8;
            uint32_t a[4][4], b[4][2];
#pragma unroll
            for (int mi = 0; mi < 4; mi++) {
                int rb = warp_m * 64 + mi * 16;
                a[mi][0] = As[(rb + g) * 20 + kk2 + tg];
                a[mi][1] = As[(rb + g + 8) * 20 + kk2 + tg];
                a[mi][2] = As[(rb + g) * 20 + kk2 + tg + 4];
                a[mi][3] = As[(rb + g + 8) * 20 + kk2 + tg + 4];
            }
#pragma unroll
            for (int ni = 0; ni < 4; ni++) {
                int nb = warp_n * 32 + ni * 8;
                b[ni][0] = Bs[(nb + g) * 20 + kk2 + tg];
                b[ni][1] = Bs[(nb + g) * 20 + kk2 + tg + 4];
            }
#pragma unroll
            for (int mi = 0; mi < 4; mi++)
#pragma unroll
                for (int ni = 0; ni < 4; ni++) {
                    asm volatile(
                        "mma.sync.aligned.m16n8k16.row.col.f32.bf16.bf16.f32 "
                        "{%0,%1,%2,%3}, {%4,%5,%6,%7}, {%8,%9}, {%0,%1,%2,%3};"
                        : "+f"(acc[mi][ni][0]), "+f"(acc[mi][ni][1]),
                          "+f"(acc[mi][ni][2]), "+f"(acc[mi][ni][3])
                        : "r"(a[mi][0]), "r"(a[mi][1]), "r"(a[mi][2]), "r"(a[mi][3]),
                          "r"(b[ni][0]), "r"(b[ni][1]));
                }
        }
        __syncthreads();
    }

    // ---- epilogue: bias + relu -> bf16x2 stores ----
#pragma unroll
    for (int mi = 0; mi < 4; mi++) {
        int rb = row0 + warp_m * 64 + mi * 16 + g;
#pragma unroll
        for (int ni = 0; ni < 4; ni++) {
            int cb = col0 + warp_n * 32 + ni * 8 + tg * 2;
            float b0 = bias[cb], b1 = bias[cb + 1];
            if (rb < N_NODES) {
                __nv_bfloat162 o = __floats2bfloat162_rn(
                    fmaxf(acc[mi][ni][0] + b0, 0.f), fmaxf(acc[mi][ni][1] + b1, 0.f));
                *(__nv_bfloat162*)(C + (size_t)rb * LDC + COFF + cb) = o;
            }
            if (rb + 8 < N_NODES) {
                __nv_bfloat162 o = __floats2bfloat162_rn(
                    fmaxf(acc[mi][ni][2] + b0, 0.f), fmaxf(acc[mi][ni][3] + b1, 0.f));
                *(__nv_bfloat162*)(C + (size_t)(rb + 8) * LDC + COFF + cb) = o;
            }
        }
    }
}

// ---------------------------------------------------------------------------
// Link prediction: sigmoid(dot(z[src], z[dst])). One warp per pair, bf16 z.
// ---------------------------------------------------------------------------
__global__ void pair_kernel(const int* __restrict__ src,
                            const int* __restrict__ dst,
                            float* __restrict__ out) {
    int p = (int)(((size_t)blockIdx.x * blockDim.x + threadIdx.x) >> 5);
    int lane = threadIdx.x & 31;
    if (p >= N_PAIRS) return;
    const uint4* zs = (const uint4*)(g_z + (size_t)src[p] * HID);
    const uint4* zd = (const uint4*)(g_z + (size_t)dst[p] * HID);
    uint4 a = zs[lane];
    uint4 b = zd[lane];
    float sum = 0.f;
    const uint32_t* ap = &a.x;
    const uint32_t* bp = &b.x;
#pragma unroll
    for (int q = 0; q < 4; q++) {
        float2 fa = __bfloat1622float2(*reinterpret_cast<const __nv_bfloat162*>(ap + q));
        float2 fb = __bfloat1622float2(*reinterpret_cast<const __nv_bfloat162*>(bp + q));
        sum += fa.x * fb.x + fa.y * fb.y;
    }
#pragma unroll
    for (int o = 16; o; o >>= 1) sum += __shfl_xor_sync(0xffffffffu, sum, o);
    if (lane == 0) out[p] = 1.0f / (1.0f + expf(-sum));
}

// ---------------------------------------------------------------------------
extern "C" void kernel_launch(void* const* d_in, const int* in_sizes, int n_in,
                              void* d_out, int out_size) {
    const float* x    = (const float*)d_in[0];
    const int*   tok  = (const int*)d_in[1];
    const float* sc   = (const float*)d_in[2];
    const int*   cat  = (const int*)d_in[3];
    const int*   eidx = (const int*)d_in[4];
    const int*   psrc = (const int*)d_in[5];
    const int*   pdst = (const int*)d_in[6];
    const float* tE   = (const float*)d_in[7];
    const float* cE   = (const float*)d_in[8];
    const float* pW   = (const float*)d_in[9];
    const float* pb   = (const float*)d_in[10];
    const float* W_l0 = (const float*)d_in[11];
    const float* b_l0 = (const float*)d_in[12];
    const float* W_r0 = (const float*)d_in[13];
    const float* W_l1 = (const float*)d_in[14];
    const float* b_l1 = (const float*)d_in[15];
    const float* W_r1 = (const float*)d_in[16];
    float* out = (float*)d_out;

    const int* esrc = eidx;
    const int* edst = eidx + N_EDGES;

    cudaFuncSetAttribute(tc_gemm<320, 512, 256>,
                         cudaFuncAttributeMaxDynamicSharedMemorySize, GEMM_SMEM_BYTES);
    cudaFuncSetAttribute(tc_gemm<512, 256, 0>,
                         cudaFuncAttributeMaxDynamicSharedMemorySize, GEMM_SMEM_BYTES);

    __nv_bfloat16 *Wt0, *Wt1, *H0, *H1, *Z;
    cudaGetSymbolAddress((void**)&Wt0, g_Wt0);
    cudaGetSymbolAddress((void**)&Wt1, g_Wt1);
    cudaGetSymbolAddress((void**)&H0, g_hcat0);
    cudaGetSymbolAddress((void**)&H1, g_hcat1);
    cudaGetSymbolAddress((void**)&Z, g_z);

    // node/block counts for the halves
    const int NB_G0A = (SPLIT_NODE + 11) / 12;              // gather0 half A
    const int NB_G0B = (N_NODES - SPLIT_NODE + 11) / 12;    // gather0 half B
    const int NB_G1A = (SPLIT_NODE + 7) / 8;                // gather1 half A
    const int NB_G1B = (N_NODES - SPLIT_NODE + 7) / 8;      // gather1 half B

    // ---- fork ----
    cudaEventRecord(g_eFork, 0);
    cudaStreamWaitEvent(g_s1, g_eFork, 0);
    cudaStreamWaitEvent(g_s2, g_eFork, 0);

    // s0: gwas
    gwas_kernel<<<GWAS_BLOCKS, 256>>>(x, tok, sc, cat, tE, cE, pW, pb);
    cudaEventRecord(g_eGwas, 0);

    // s1: CSR build
    zero_deg_kernel<<<(N_NODES / 4 + 255) / 256, 256, 0, g_s1>>>();
    count_kernel<<<(N_EDGES + 255) / 256, 256, 0, g_s1>>>(edst);
    scanA_kernel<<<SCAN_BLOCKS, 1024, 0, g_s1>>>();
    scanB_kernel<<<1, 32, 0, g_s1>>>();
    scanC_kernel<<<SCAN_BLOCKS, 1024, 0, g_s1>>>();
    fill_kernel<<<(N_EDGES + 255) / 256, 256, 0, g_s1>>>(esrc, edst);
    cudaEventRecord(g_eCSR, g_s1);

    // s2: weight transposes
    wstack_kernel<<<dim3(320 / 32, HID / 32), dim3(32, 8), 0, g_s2>>>(
        W_l0, W_r0, Wt0, 160, 320);
    cudaEventRecord(g_eW0, g_s2);
    wstack_kernel<<<dim3(512 / 32, HID / 32), dim3(32, 8), 0, g_s2>>>(
        W_l1, W_r1, Wt1, 256, 512);
    cudaEventRecord(g_eW1, g_s2);

    // ---- layer 0, pipelined halves ----
    // s0 (half A): needs CSR (gwas is in s0 program order)
    cudaStreamWaitEvent(0, g_eCSR, 0);
    gather_kernel<0><<<NB_G0A, 256>>>(0, SPLIT_NODE);
    cudaStreamWaitEvent(0, g_eW0, 0);
    tc_gemm<320, 512, 256><<<dim3(TILES_A, 2), 256, GEMM_SMEM_BYTES>>>(
        H0, Wt0, b_l0, H1, 0);
    cudaEventRecord(g_eM0A, 0);

    // s1 (half B): needs gwas (CSR is in s1 program order)
    cudaStreamWaitEvent(g_s1, g_eGwas, 0);
    gather_kernel<0><<<NB_G0B, 256, 0, g_s1>>>(SPLIT_NODE, N_NODES);
    cudaStreamWaitEvent(g_s1, g_eW0, 0);
    tc_gemm<320, 512, 256><<<dim3(TILES_B, 2), 256, GEMM_SMEM_BYTES, g_s1>>>(
        H0, Wt0, b_l0, H1, TILES_A);
    cudaEventRecord(g_eM0B, g_s1);

    // ---- layer 1, pipelined halves ----
    // gather1 halves need BOTH gemm0 halves (neighbors span all nodes)
    cudaStreamWaitEvent(0, g_eM0B, 0);
    gather_kernel<1><<<NB_G1A, 256>>>(0, SPLIT_NODE);
    cudaStreamWaitEvent(0, g_eW1, 0);
    tc_gemm<512, 256, 0><<<dim3(TILES_A, 2), 256, GEMM_SMEM_BYTES>>>(
        H1, Wt1, b_l1, Z, 0);

    cudaStreamWaitEvent(g_s1, g_eM0A, 0);
    gather_kernel<1><<<NB_G1B, 256, 0, g_s1>>>(SPLIT_NODE, N_NODES);
    cudaStreamWaitEvent(g_s1, g_eW1, 0);
    tc_gemm<512, 256, 0><<<dim3(TILES_B, 2), 256, GEMM_SMEM_BYTES, g_s1>>>(
        H1, Wt1, b_l1, Z, TILES_A);
    cudaEventRecord(g_eM1B, g_s1);

    // ---- pair (needs both gemm1 halves) ----
    cudaStreamWaitEvent(0, g_eM1B, 0);
    pair_kernel<<<(N_PAIRS + 7) / 8, 256>>>(psrc, pdst, out);
}